// round 14
// baseline (speedup 1.0000x reference)
#include <cuda_runtime.h>
#include <cuda_fp16.h>
#include <cstdint>

#define NB 8
#define NN 2048
#define DF 128
#define NF 128

// ---------------- scratch (device globals; no allocation allowed) ----------
__device__ float  g_colsum[NB * NN];
__device__ float  g_d[NB * NN];
__device__ __half g_A16[(size_t)NB * NN * NN];  // fp16 cast of A
__device__ __half g_Xs16[NB * NN * DF];         // fp16 of Xs = d*X, [b][j][f]
__device__ __half g_W16[DF * NF];               // fp16 of W

// ---------------- helpers ---------------------------------------------------
__device__ __forceinline__ uint32_t smem_u32(const void* p) {
    uint32_t a;
    asm("{ .reg .u64 t; cvta.to.shared.u64 t, %1; cvt.u32.u64 %0, t; }"
        : "=r"(a) : "l"(p));
    return a;
}
__device__ __forceinline__ void ldmatrix_x4(uint32_t* r, uint32_t addr) {
    asm volatile("ldmatrix.sync.aligned.m8n8.x4.shared.b16 {%0,%1,%2,%3}, [%4];"
                 : "=r"(r[0]), "=r"(r[1]), "=r"(r[2]), "=r"(r[3]) : "r"(addr));
}
__device__ __forceinline__ void ldmatrix_x4_trans(uint32_t* r, uint32_t addr) {
    asm volatile("ldmatrix.sync.aligned.m8n8.x4.trans.shared.b16 {%0,%1,%2,%3}, [%4];"
                 : "=r"(r[0]), "=r"(r[1]), "=r"(r[2]), "=r"(r[3]) : "r"(addr));
}
__device__ __forceinline__ void mma16816(float* d, const uint32_t* a, const uint32_t* b) {
    asm volatile(
        "mma.sync.aligned.m16n8k16.row.col.f32.f16.f16.f32 "
        "{%0,%1,%2,%3}, {%4,%5,%6,%7}, {%8,%9}, {%0,%1,%2,%3};"
        : "+f"(d[0]), "+f"(d[1]), "+f"(d[2]), "+f"(d[3])
        : "r"(a[0]), "r"(a[1]), "r"(a[2]), "r"(a[3]), "r"(b[0]), "r"(b[1]));
}
__device__ __forceinline__ void cp_async16(uint32_t saddr, const void* gaddr) {
    asm volatile("cp.async.cg.shared.global [%0], [%1], 16;"
                 :: "r"(saddr), "l"(gaddr) : "memory");
}
__device__ __forceinline__ void cp_commit() {
    asm volatile("cp.async.commit_group;" ::: "memory");
}

// ---------------------------------------------------------------------------
// 1. misc: zero colsum accumulator + convert W -> fp16 (one launch)
// ---------------------------------------------------------------------------
__global__ void k_misc(const float* __restrict__ W) {
    int bid = blockIdx.x;
    if (bid < 64) {                       // zero 16384 colsum entries
        g_colsum[bid * 256 + threadIdx.x] = 0.0f;
    } else {                              // convert W: 4096 float4
        int q = (bid - 64) * 256 + threadIdx.x;
        float4 v = ((const float4*)W)[q];
        __half2 h01 = __floats2half2_rn(v.x, v.y);
        __half2 h23 = __floats2half2_rn(v.z, v.w);
        *(uint2*)&g_W16[q * 4] = make_uint2(*(uint32_t*)&h01, *(uint32_t*)&h23);
    }
}

// ---------------------------------------------------------------------------
// 2. fused: copy A -> outA, emit A16 = fp16(A), column sums
// ---------------------------------------------------------------------------
__global__ __launch_bounds__(256) void k_copy_colsum(const float* __restrict__ A,
                                                     float* __restrict__ outA) {
    int b  = blockIdx.z;
    int c4 = blockIdx.x * 256 + threadIdx.x;
    int r0 = blockIdx.y * 128;
    const float4* Ab = (const float4*)(A    + (size_t)b * NN * NN) + c4;
    float4*       Ob = (float4*)      (outA + (size_t)b * NN * NN) + c4;
    __half*       Hb = g_A16 + (size_t)b * NN * NN;
    float4 s = make_float4(0.f, 0.f, 0.f, 0.f);
    #pragma unroll 4
    for (int r = 0; r < 128; r++) {
        float4 v = Ab[(size_t)(r0 + r) * (NN / 4)];
        Ob[(size_t)(r0 + r) * (NN / 4)] = v;
        __half2 h01 = __floats2half2_rn(v.x, v.y);
        __half2 h23 = __floats2half2_rn(v.z, v.w);
        *(uint2*)&Hb[(size_t)(r0 + r) * NN + c4 * 4] =
            make_uint2(*(uint32_t*)&h01, *(uint32_t*)&h23);
        s.x += v.x; s.y += v.y; s.z += v.z; s.w += v.w;
    }
    float* cs = &g_colsum[b * NN + c4 * 4];
    atomicAdd(cs + 0, s.x);
    atomicAdd(cs + 1, s.y);
    atomicAdd(cs + 2, s.z);
    atomicAdd(cs + 3, s.w);
}

// ---------------------------------------------------------------------------
// 3. d = rsqrt(colsum+1); Xs16 = fp16(d*X)
// ---------------------------------------------------------------------------
__global__ __launch_bounds__(256) void k_dscale(const float* __restrict__ X) {
    int q   = blockIdx.x * 256 + threadIdx.x;          // float4 index
    int row = q >> 5;                                  // 32 float4 per row
    float dv = rsqrtf(g_colsum[row] + 1.0f);
    if ((q & 31) == 0) g_d[row] = dv;
    float4 v = ((const float4*)X)[q];
    __half2 h01 = __floats2half2_rn(dv * v.x, dv * v.y);
    __half2 h23 = __floats2half2_rn(dv * v.z, dv * v.w);
    *(uint2*)&g_Xs16[q * 4] = make_uint2(*(uint32_t*)&h01, *(uint32_t*)&h23);
}

// ---------------------------------------------------------------------------
// 4. FULLY FUSED GEMM, 512 threads / 16 warps (4x4):
//    acc = A16 @ Xs16 (K=2048, 4-stage cp.async), then in-CTA
//    H = relu(Y @ W16) with Y staged in smem. Each warp: 32x32 slice.
// ---------------------------------------------------------------------------
#define KT 32
#define NSTAGE 4
#define A_STR 40
#define B_STR 136
#define A_BYTES (128 * A_STR * 2)     // 10240
#define B_BYTES (KT * B_STR * 2)      // 8704
#define STG_BYTES (A_BYTES + B_BYTES) // 18944
#define W_STR 136
#define W_BYTES_SM (128 * W_STR * 2)  // 34816
#define DYN_SMEM (NSTAGE * STG_BYTES + W_BYTES_SM)  // 110592

__global__ __launch_bounds__(512, 1) void k_mma(const float* __restrict__ X,
                                                float* __restrict__ outH) {
    extern __shared__ char smem[];
    int tid  = threadIdx.x;
    int wid  = tid >> 5;
    int lane = tid & 31;
    int wm   = wid >> 2;        // 0..3 (32 rows each)
    int wn   = wid & 3;         // 0..3 (32 cols each)
    int b    = blockIdx.y;
    int m0   = blockIdx.x * 128;

    const __half* AG = g_A16  + (size_t)b * NN * NN + (size_t)m0 * NN;
    const __half* BG = g_Xs16 + (size_t)b * NN * DF;

    uint32_t sb    = smem_u32(smem);
    uint32_t wBase = sb + NSTAGE * STG_BYTES;

    // ---- stage W16 into smem (persists through mainloop): 2048 chunks, 4/thr
    #pragma unroll
    for (int i = 0; i < 4; i++) {
        int q = tid + i * 512, row = q >> 4, u = q & 15;
        cp_async16(wBase + (uint32_t)(row * W_STR + u * 8) * 2,
                   &g_W16[row * NF + u * 8]);
    }
    cp_commit();

    float acc[2][4][4];
    #pragma unroll
    for (int i = 0; i < 2; i++)
        #pragma unroll
        for (int j = 0; j < 4; j++)
            #pragma unroll
            for (int c = 0; c < 4; c++) acc[i][j][c] = 0.0f;

    // issue tile t into stage s: A 512 chunks (1/thr), B 512 chunks (1/thr)
    auto issue = [&](int t, int s) {
        int k0 = t * KT;
        uint32_t ap = sb + s * STG_BYTES;
        uint32_t bp = ap + A_BYTES;
        {   // A: row = tid>>2 (4 chunks/row), c = tid&3
            int row = tid >> 2, c = tid & 3;
            cp_async16(ap + (uint32_t)(row * A_STR + c * 8) * 2,
                       AG + (size_t)row * NN + k0 + c * 8);
        }
        {   // B: row = tid>>4 (16 chunks/row), u = tid&15
            int row = tid >> 4, u = tid & 15;
            cp_async16(bp + (uint32_t)(row * B_STR + u * 8) * 2,
                       BG + (size_t)(k0 + row) * DF + u * 8);
        }
        cp_commit();
    };

    #pragma unroll
    for (int s = 0; s < NSTAGE - 1; s++) issue(s, s);

    const int NT = NN / KT;     // 64
    for (int t = 0; t < NT; t++) {
        asm volatile("cp.async.wait_group %0;" :: "n"(NSTAGE - 2) : "memory");
        __syncthreads();
        if (t + NSTAGE - 1 < NT) issue(t + NSTAGE - 1, (t + NSTAGE - 1) % NSTAGE);
        else cp_commit();

        int s = t % NSTAGE;
        uint32_t aBase = sb + s * STG_BYTES;
        uint32_t bBase = aBase + A_BYTES;
        #pragma unroll
        for (int ks = 0; ks < KT; ks += 16) {
            uint32_t af[2][4];
            #pragma unroll
            for (int mf = 0; mf < 2; mf++) {
                int row = wm * 32 + mf * 16 + (lane & 7) + ((lane >> 3) & 1) * 8;
                int col = ks + (lane >> 4) * 8;
                ldmatrix_x4(af[mf], aBase + (row * A_STR + col) * 2);
            }
            uint32_t bf[4][2];
            #pragma unroll
            for (int nh = 0; nh < 2; nh++) {
                int row = ks + ((lane >> 3) & 1) * 8 + (lane & 7);
                int col = wn * 32 + nh * 16 + (lane >> 4) * 8;
                uint32_t t4[4];
                ldmatrix_x4_trans(t4, bBase + (row * B_STR + col) * 2);
                bf[2 * nh][0] = t4[0]; bf[2 * nh][1] = t4[1];
                bf[2 * nh + 1][0] = t4[2]; bf[2 * nh + 1][1] = t4[3];
            }
            #pragma unroll
            for (int mf = 0; mf < 2; mf++)
                #pragma unroll
                for (int nf = 0; nf < 4; nf++)
                    mma16816(acc[mf][nf], af[mf], bf[nf]);
        }
        __syncthreads();
    }

    // ---- epilogue 1: Y16[i,f] = fp16(d*acc + d^2*X) -> smem (stage region)
    uint32_t yBase = sb;                 // Y tile: 128 x 128 fp16, stride W_STR
    const float* Xb = X + (size_t)b * NN * DF;
    #pragma unroll
    for (int mf = 0; mf < 2; mf++) {
        int rl = wm * 32 + mf * 16 + (lane >> 2);     // local row
        int row = m0 + rl;
        float d0 = g_d[b * NN + row];
        float d1 = g_d[b * NN + row + 8];
        float e0 = d0 * d0, e1 = d1 * d1;
        #pragma unroll
        for (int nf = 0; nf < 4; nf++) {
            int col = wn * 32 + nf * 8 + (lane & 3) * 2;
            float2 x0 = *(const float2*)&Xb[(size_t)row * DF + col];
            float2 x1 = *(const float2*)&Xb[(size_t)(row + 8) * DF + col];
            __half2 o0 = __floats2half2_rn(d0 * acc[mf][nf][0] + e0 * x0.x,
                                           d0 * acc[mf][nf][1] + e0 * x0.y);
            __half2 o1 = __floats2half2_rn(d1 * acc[mf][nf][2] + e1 * x1.x,
                                           d1 * acc[mf][nf][3] + e1 * x1.y);
            *(__half2*)(smem + (rl * W_STR + col) * 2)       = o0;
            *(__half2*)(smem + ((rl + 8) * W_STR + col) * 2) = o1;
        }
    }
    __syncthreads();

    // ---- epilogue 2: H = relu(Y @ W16), K=128, write fp32 ----
    float acc2[2][4][4];
    #pragma unroll
    for (int i = 0; i < 2; i++)
        #pragma unroll
        for (int j = 0; j < 4; j++)
            #pragma unroll
            for (int c = 0; c < 4; c++) acc2[i][j][c] = 0.0f;

    #pragma unroll
    for (int ks = 0; ks < DF; ks += 16) {
        uint32_t af[2][4];
        #pragma unroll
        for (int mf = 0; mf < 2; mf++) {
            int row = wm * 32 + mf * 16 + (lane & 7) + ((lane >> 3) & 1) * 8;
            int col = ks + (lane >> 4) * 8;
            ldmatrix_x4(af[mf], yBase + (row * W_STR + col) * 2);
        }
        uint32_t bf[4][2];
        #pragma unroll
        for (int nh = 0; nh < 2; nh++) {
            int row = ks + ((lane >> 3) & 1) * 8 + (lane & 7);
            int col = wn * 32 + nh * 16 + (lane >> 4) * 8;
            uint32_t t4[4];
            ldmatrix_x4_trans(t4, wBase + (row * W_STR + col) * 2);
            bf[2 * nh][0] = t4[0]; bf[2 * nh][1] = t4[1];
            bf[2 * nh + 1][0] = t4[2]; bf[2 * nh + 1][1] = t4[3];
        }
        #pragma unroll
        for (int mf = 0; mf < 2; mf++)
            #pragma unroll
            for (int nf = 0; nf < 4; nf++)
                mma16816(acc2[mf][nf], af[mf], bf[nf]);
    }

    float* Hb = outH + ((size_t)b * NN + m0) * NF;
    #pragma unroll
    for (int mf = 0; mf < 2; mf++) {
        int rl = wm * 32 + mf * 16 + (lane >> 2);
        #pragma unroll
        for (int nf = 0; nf < 4; nf++) {
            int col = wn * 32 + nf * 8 + (lane & 3) * 2;
            float2 o0 = make_float2(fmaxf(acc2[mf][nf][0], 0.f),
                                    fmaxf(acc2[mf][nf][1], 0.f));
            float2 o1 = make_float2(fmaxf(acc2[mf][nf][2], 0.f),
                                    fmaxf(acc2[mf][nf][3], 0.f));
            *(float2*)&Hb[(size_t)rl * NF + col] = o0;
            *(float2*)&Hb[(size_t)(rl + 8) * NF + col] = o1;
        }
    }
}

// ---------------------------------------------------------------------------
extern "C" void kernel_launch(void* const* d_in, const int* in_sizes, int n_in,
                              void* d_out, int out_size) {
    const float* A = (const float*)d_in[0];
    const float* X = (const float*)d_in[1];
    const float* W = (const float*)d_in[2];

    float* outA = (float*)d_out;
    float* outH = (float*)d_out + (size_t)NB * NN * NN;

    static bool attr_set = false;
    if (!attr_set) {
        cudaFuncSetAttribute(k_mma, cudaFuncAttributeMaxDynamicSharedMemorySize, DYN_SMEM);
        attr_set = true;
    }

    k_misc<<<80, 256>>>(W);
    k_copy_colsum<<<dim3(NN / 4 / 256, NN / 128, NB), 256>>>(A, outA);
    k_dscale<<<(NB * NN * DF / 4) / 256, 256>>>(X);
    k_mma<<<dim3(NN / 128, NB), 512, DYN_SMEM>>>(X, outH);
}

// round 15
// speedup vs baseline: 1.0762x; 1.0762x over previous
#include <cuda_runtime.h>
#include <cuda_fp16.h>
#include <cstdint>

#define NB 8
#define NN 2048
#define DF 128
#define NF 128

// ---------------- scratch (device globals; no allocation allowed) ----------
__device__ float  g_colsum[NB * NN];
__device__ float  g_d[NB * NN];
__device__ __half g_A16[(size_t)NB * NN * NN];  // fp16 cast of A
__device__ __half g_Xs16[NB * NN * DF];         // fp16 of Xs = d*X, [b][j][f]
__device__ __half g_W16[DF * NF];               // fp16 of W

// ---------------- helpers ---------------------------------------------------
__device__ __forceinline__ uint32_t smem_u32(const void* p) {
    uint32_t a;
    asm("{ .reg .u64 t; cvta.to.shared.u64 t, %1; cvt.u32.u64 %0, t; }"
        : "=r"(a) : "l"(p));
    return a;
}
__device__ __forceinline__ void ldmatrix_x4(uint32_t* r, uint32_t addr) {
    asm volatile("ldmatrix.sync.aligned.m8n8.x4.shared.b16 {%0,%1,%2,%3}, [%4];"
                 : "=r"(r[0]), "=r"(r[1]), "=r"(r[2]), "=r"(r[3]) : "r"(addr));
}
__device__ __forceinline__ void ldmatrix_x4_trans(uint32_t* r, uint32_t addr) {
    asm volatile("ldmatrix.sync.aligned.m8n8.x4.trans.shared.b16 {%0,%1,%2,%3}, [%4];"
                 : "=r"(r[0]), "=r"(r[1]), "=r"(r[2]), "=r"(r[3]) : "r"(addr));
}
__device__ __forceinline__ void mma16816(float* d, const uint32_t* a, const uint32_t* b) {
    asm volatile(
        "mma.sync.aligned.m16n8k16.row.col.f32.f16.f16.f32 "
        "{%0,%1,%2,%3}, {%4,%5,%6,%7}, {%8,%9}, {%0,%1,%2,%3};"
        : "+f"(d[0]), "+f"(d[1]), "+f"(d[2]), "+f"(d[3])
        : "r"(a[0]), "r"(a[1]), "r"(a[2]), "r"(a[3]), "r"(b[0]), "r"(b[1]));
}
__device__ __forceinline__ void cp_async16(uint32_t saddr, const void* gaddr) {
    asm volatile("cp.async.cg.shared.global [%0], [%1], 16;"
                 :: "r"(saddr), "l"(gaddr) : "memory");
}
__device__ __forceinline__ void cp_commit() {
    asm volatile("cp.async.commit_group;" ::: "memory");
}

// ---------------------------------------------------------------------------
// 1. misc: zero colsum accumulator + convert W -> fp16 (one launch)
// ---------------------------------------------------------------------------
__global__ void k_misc(const float* __restrict__ W) {
    int bid = blockIdx.x;
    if (bid < 64) {
        g_colsum[bid * 256 + threadIdx.x] = 0.0f;
    } else {
        int q = (bid - 64) * 256 + threadIdx.x;
        float4 v = ((const float4*)W)[q];
        __half2 h01 = __floats2half2_rn(v.x, v.y);
        __half2 h23 = __floats2half2_rn(v.z, v.w);
        *(uint2*)&g_W16[q * 4] = make_uint2(*(uint32_t*)&h01, *(uint32_t*)&h23);
    }
}

// ---------------------------------------------------------------------------
// 2. fused: copy A -> outA, emit A16 = fp16(A), column sums
// ---------------------------------------------------------------------------
__global__ __launch_bounds__(256) void k_copy_colsum(const float* __restrict__ A,
                                                     float* __restrict__ outA) {
    int b  = blockIdx.z;
    int c4 = blockIdx.x * 256 + threadIdx.x;
    int r0 = blockIdx.y * 128;
    const float4* Ab = (const float4*)(A    + (size_t)b * NN * NN) + c4;
    float4*       Ob = (float4*)      (outA + (size_t)b * NN * NN) + c4;
    __half*       Hb = g_A16 + (size_t)b * NN * NN;
    float4 s = make_float4(0.f, 0.f, 0.f, 0.f);
    #pragma unroll 4
    for (int r = 0; r < 128; r++) {
        float4 v = Ab[(size_t)(r0 + r) * (NN / 4)];
        Ob[(size_t)(r0 + r) * (NN / 4)] = v;
        __half2 h01 = __floats2half2_rn(v.x, v.y);
        __half2 h23 = __floats2half2_rn(v.z, v.w);
        *(uint2*)&Hb[(size_t)(r0 + r) * NN + c4 * 4] =
            make_uint2(*(uint32_t*)&h01, *(uint32_t*)&h23);
        s.x += v.x; s.y += v.y; s.z += v.z; s.w += v.w;
    }
    float* cs = &g_colsum[b * NN + c4 * 4];
    atomicAdd(cs + 0, s.x);
    atomicAdd(cs + 1, s.y);
    atomicAdd(cs + 2, s.z);
    atomicAdd(cs + 3, s.w);
}

// ---------------------------------------------------------------------------
// 3. d = rsqrt(colsum+1); Xs16 = fp16(d*X)
// ---------------------------------------------------------------------------
__global__ __launch_bounds__(256) void k_dscale(const float* __restrict__ X) {
    int q   = blockIdx.x * 256 + threadIdx.x;
    int row = q >> 5;
    float dv = rsqrtf(g_colsum[row] + 1.0f);
    if ((q & 31) == 0) g_d[row] = dv;
    float4 v = ((const float4*)X)[q];
    __half2 h01 = __floats2half2_rn(dv * v.x, dv * v.y);
    __half2 h23 = __floats2half2_rn(dv * v.z, dv * v.w);
    *(uint2*)&g_Xs16[q * 4] = make_uint2(*(uint32_t*)&h01, *(uint32_t*)&h23);
}

// ---------------------------------------------------------------------------
// 4. FULLY FUSED GEMM: acc = A16 @ Xs16 (K=2048, KT=64, 3-stage cp.async,
//    ONE barrier per tile), then in-CTA H = relu(Y @ W16).
//    256 threads, 8 warps (2x4), 4x4 frags/warp.
// ---------------------------------------------------------------------------
#define KT 64
#define NSTAGE 3
#define A_STR 72                       // 64 + 8 pad halves; 144B = 16 mod 128 ok
#define B_STR 136                      // 128 + 8 pad halves; 272B = 16 mod 128 ok
#define A_BYTES (128 * A_STR * 2)      // 18432
#define B_BYTES (KT * B_STR * 2)       // 17408
#define STG_BYTES (A_BYTES + B_BYTES)  // 35840
#define W_STR 136
#define W_BYTES_SM (128 * W_STR * 2)   // 34816
#define DYN_SMEM (NSTAGE * STG_BYTES + W_BYTES_SM)  // 142336

__global__ __launch_bounds__(256, 1) void k_mma(const float* __restrict__ X,
                                                float* __restrict__ outH) {
    extern __shared__ char smem[];
    int tid  = threadIdx.x;
    int wid  = tid >> 5;
    int lane = tid & 31;
    int wm   = wid >> 2;        // 0..1 (64 rows each)
    int wn   = wid & 3;         // 0..3 (32 cols each)
    int b    = blockIdx.y;
    int m0   = blockIdx.x * 128;

    const __half* AG = g_A16  + (size_t)b * NN * NN + (size_t)m0 * NN;
    const __half* BG = g_Xs16 + (size_t)b * NN * DF;

    uint32_t sb    = smem_u32(smem);
    uint32_t wBase = sb + NSTAGE * STG_BYTES;

    // ---- stage W16 into smem (persists through mainloop): 2048 chunks, 8/thr
    #pragma unroll
    for (int i = 0; i < 8; i++) {
        int q = tid + i * 256, row = q >> 4, u = q & 15;
        cp_async16(wBase + (uint32_t)(row * W_STR + u * 8) * 2,
                   &g_W16[row * NF + u * 8]);
    }
    cp_commit();

    float acc[4][4][4];
    #pragma unroll
    for (int i = 0; i < 4; i++)
        #pragma unroll
        for (int j = 0; j < 4; j++)
            #pragma unroll
            for (int c = 0; c < 4; c++) acc[i][j][c] = 0.0f;

    // issue tile t into stage s: A 1024 chunks (4/thr), B 1024 chunks (4/thr)
    auto issue = [&](int t, int s) {
        int k0 = t * KT;
        uint32_t ap = sb + s * STG_BYTES;
        uint32_t bp = ap + A_BYTES;
        #pragma unroll
        for (int i = 0; i < 4; i++) {
            int q = tid + i * 256, row = q >> 3, c = q & 7;   // 8 chunks per A row
            cp_async16(ap + (uint32_t)(row * A_STR + c * 8) * 2,
                       AG + (size_t)row * NN + k0 + c * 8);
        }
        #pragma unroll
        for (int i = 0; i < 4; i++) {
            int q = tid + i * 256, row = q >> 4, u = q & 15;  // 16 chunks per B row
            cp_async16(bp + (uint32_t)(row * B_STR + u * 8) * 2,
                       BG + (size_t)(k0 + row) * DF + u * 8);
        }
        cp_commit();
    };

    #pragma unroll
    for (int s = 0; s < NSTAGE - 1; s++) issue(s, s);

    const int NT = NN / KT;     // 32
    for (int t = 0; t < NT; t++) {
        asm volatile("cp.async.wait_group %0;" :: "n"(NSTAGE - 2) : "memory");
        __syncthreads();        // sole barrier: all warps done with tile t-1
        if (t + NSTAGE - 1 < NT) issue(t + NSTAGE - 1, (t + NSTAGE - 1) % NSTAGE);
        else cp_commit();

        int s = t % NSTAGE;
        uint32_t aBase = sb + s * STG_BYTES;
        uint32_t bBase = aBase + A_BYTES;
        #pragma unroll
        for (int ks = 0; ks < KT; ks += 16) {
            uint32_t af[4][4];
            #pragma unroll
            for (int mf = 0; mf < 4; mf++) {
                int row = wm * 64 + mf * 16 + (lane & 7) + ((lane >> 3) & 1) * 8;
                int col = ks + (lane >> 4) * 8;
                ldmatrix_x4(af[mf], aBase + (row * A_STR + col) * 2);
            }
            uint32_t bf[4][2];
            #pragma unroll
            for (int nh = 0; nh < 2; nh++) {
                int row = ks + ((lane >> 3) & 1) * 8 + (lane & 7);
                int col = wn * 32 + nh * 16 + (lane >> 4) * 8;
                uint32_t t4[4];
                ldmatrix_x4_trans(t4, bBase + (row * B_STR + col) * 2);
                bf[2 * nh][0] = t4[0]; bf[2 * nh][1] = t4[1];
                bf[2 * nh + 1][0] = t4[2]; bf[2 * nh + 1][1] = t4[3];
            }
            #pragma unroll
            for (int mf = 0; mf < 4; mf++)
                #pragma unroll
                for (int nf = 0; nf < 4; nf++)
                    mma16816(acc[mf][nf], af[mf], bf[nf]);
        }
    }
    __syncthreads();            // all compute done before reusing stage 0 for Y

    // ---- epilogue 1: Y16[i,f] = fp16(d*acc + d^2*X) -> smem ----
    uint32_t yBase = sb;        // Y tile: 128 x 128 fp16, stride W_STR
    const float* Xb = X + (size_t)b * NN * DF;
    #pragma unroll
    for (int mf = 0; mf < 4; mf++) {
        int rl = wm * 64 + mf * 16 + (lane >> 2);
        int row = m0 + rl;
        float d0 = g_d[b * NN + row];
        float d1 = g_d[b * NN + row + 8];
        float e0 = d0 * d0, e1 = d1 * d1;
        #pragma unroll
        for (int nf = 0; nf < 4; nf++) {
            int col = wn * 32 + nf * 8 + (lane & 3) * 2;
            float2 x0 = *(const float2*)&Xb[(size_t)row * DF + col];
            float2 x1 = *(const float2*)&Xb[(size_t)(row + 8) * DF + col];
            __half2 o0 = __floats2half2_rn(d0 * acc[mf][nf][0] + e0 * x0.x,
                                           d0 * acc[mf][nf][1] + e0 * x0.y);
            __half2 o1 = __floats2half2_rn(d1 * acc[mf][nf][2] + e1 * x1.x,
                                           d1 * acc[mf][nf][3] + e1 * x1.y);
            *(__half2*)(smem + (rl * W_STR + col) * 2)       = o0;
            *(__half2*)(smem + ((rl + 8) * W_STR + col) * 2) = o1;
        }
    }
    __syncthreads();

    // ---- epilogue 2: H = relu(Y @ W16), K=128, write fp32 ----
    float acc2[4][4][4];
    #pragma unroll
    for (int i = 0; i < 4; i++)
        #pragma unroll
        for (int j = 0; j < 4; j++)
            #pragma unroll
            for (int c = 0; c < 4; c++) acc2[i][j][c] = 0.0f;

    #pragma unroll
    for (int ks = 0; ks < DF; ks += 16) {
        uint32_t af[4][4];
        #pragma unroll
        for (int mf = 0; mf < 4; mf++) {
            int row = wm * 64 + mf * 16 + (lane & 7) + ((lane >> 3) & 1) * 8;
            int col = ks + (lane >> 4) * 8;
            ldmatrix_x4(af[mf], yBase + (row * W_STR + col) * 2);
        }
        uint32_t bf[4][2];
        #pragma unroll
        for (int nh = 0; nh < 2; nh++) {
            int row = ks + ((lane >> 3) & 1) * 8 + (lane & 7);
            int col = wn * 32 + nh * 16 + (lane >> 4) * 8;
            uint32_t t4[4];
            ldmatrix_x4_trans(t4, wBase + (row * W_STR + col) * 2);
            bf[2 * nh][0] = t4[0]; bf[2 * nh][1] = t4[1];
            bf[2 * nh + 1][0] = t4[2]; bf[2 * nh + 1][1] = t4[3];
        }
        #pragma unroll
        for (int mf = 0; mf < 4; mf++)
            #pragma unroll
            for (int nf = 0; nf < 4; nf++)
                mma16816(acc2[mf][nf], af[mf], bf[nf]);
    }

    float* Hb = outH + ((size_t)b * NN + m0) * NF;
    #pragma unroll
    for (int mf = 0; mf < 4; mf++) {
        int rl = wm * 64 + mf * 16 + (lane >> 2);
        #pragma unroll
        for (int nf = 0; nf < 4; nf++) {
            int col = wn * 32 + nf * 8 + (lane & 3) * 2;
            float2 o0 = make_float2(fmaxf(acc2[mf][nf][0], 0.f),
                                    fmaxf(acc2[mf][nf][1], 0.f));
            float2 o1 = make_float2(fmaxf(acc2[mf][nf][2], 0.f),
                                    fmaxf(acc2[mf][nf][3], 0.f));
            *(float2*)&Hb[(size_t)rl * NF + col] = o0;
            *(float2*)&Hb[(size_t)(rl + 8) * NF + col] = o1;
        }
    }
}

// ---------------------------------------------------------------------------
extern "C" void kernel_launch(void* const* d_in, const int* in_sizes, int n_in,
                              void* d_out, int out_size) {
    const float* A = (const float*)d_in[0];
    const float* X = (const float*)d_in[1];
    const float* W = (const float*)d_in[2];

    float* outA = (float*)d_out;
    float* outH = (float*)d_out + (size_t)NB * NN * NN;

    static bool attr_set = false;
    if (!attr_set) {
        cudaFuncSetAttribute(k_mma, cudaFuncAttributeMaxDynamicSharedMemorySize, DYN_SMEM);
        attr_set = true;
    }

    k_misc<<<80, 256>>>(W);
    k_copy_colsum<<<dim3(NN / 4 / 256, NN / 128, NB), 256>>>(A, outA);
    k_dscale<<<(NB * NN * DF / 4) / 256, 256>>>(X);
    k_mma<<<dim3(NN / 128, NB), 256, DYN_SMEM>>>(X, outH);
}